// round 1
// baseline (speedup 1.0000x reference)
#include <cuda_runtime.h>

// Weight layout in constant memory:
// [0:4)  w_ih (i,f,g,o)   [4:8)  w_hh   [8:12) b_ih   [12:16) b_hh
// [16:34) w_lin (18)      [34]   b_lin
__constant__ float c_w[35];

__device__ __forceinline__ float tanh_fast(float x) {
    float y;
    asm("tanh.approx.f32 %0, %1;" : "=f"(y) : "f"(x));
    return y;
}

// sigmoid(x) = 0.5 * tanh(0.5*x) + 0.5  -> 1 MUFU + 1 FMUL + 1 FFMA
__device__ __forceinline__ float sigmoid_fast(float x) {
    return fmaf(tanh_fast(0.5f * x), 0.5f, 0.5f);
}

__global__ __launch_bounds__(256) void lstm_lin_kernel(
    const float* __restrict__ x, float* __restrict__ out, int nrows)
{
    int r = blockIdx.x * blockDim.x + threadIdx.x;
    if (r >= nrows) return;

    const float wi = c_w[0], wf = c_w[1], wg = c_w[2], wo = c_w[3];
    const float ui = c_w[4], uf = c_w[5], ug = c_w[6], uo = c_w[7];
    const float bi = c_w[8]  + c_w[12];
    const float bf = c_w[9]  + c_w[13];
    const float bg = c_w[10] + c_w[14];
    const float bo = c_w[11] + c_w[15];

    // 18 floats per output row, 8B-aligned (72 bytes per row)
    const float2* p = reinterpret_cast<const float2*>(x) + (size_t)r * 9;
    float v[18];
#pragma unroll
    for (int j = 0; j < 9; j++) {
        float2 t = __ldg(p + j);
        v[2 * j]     = t.x;
        v[2 * j + 1] = t.y;
    }

    float acc = c_w[34];

#pragma unroll
    for (int e = 0; e < 6; e++) {
        const float x0 = v[e * 3 + 0];
        const float x1 = v[e * 3 + 1];
        const float x2 = v[e * 3 + 2];

        // ---- step 0: h=0, c=0 -> forget gate is dead (f*c = 0) ----
        float i0 = sigmoid_fast(fmaf(wi, x0, bi));
        float g0 = tanh_fast  (fmaf(wg, x0, bg));
        float o0 = sigmoid_fast(fmaf(wo, x0, bo));
        float c  = i0 * g0;
        float h  = o0 * tanh_fast(c);
        acc = fmaf(h, c_w[16 + e * 3 + 0], acc);

        // ---- step 1 ----
        float i1 = sigmoid_fast(fmaf(ui, h, fmaf(wi, x1, bi)));
        float f1 = sigmoid_fast(fmaf(uf, h, fmaf(wf, x1, bf)));
        float g1 = tanh_fast  (fmaf(ug, h, fmaf(wg, x1, bg)));
        float o1 = sigmoid_fast(fmaf(uo, h, fmaf(wo, x1, bo)));
        c = fmaf(f1, c, i1 * g1);
        h = o1 * tanh_fast(c);
        acc = fmaf(h, c_w[16 + e * 3 + 1], acc);

        // ---- step 2 ----
        float i2 = sigmoid_fast(fmaf(ui, h, fmaf(wi, x2, bi)));
        float f2 = sigmoid_fast(fmaf(uf, h, fmaf(wf, x2, bf)));
        float g2 = tanh_fast  (fmaf(ug, h, fmaf(wg, x2, bg)));
        float o2 = sigmoid_fast(fmaf(uo, h, fmaf(wo, x2, bo)));
        c = fmaf(f2, c, i2 * g2);
        h = o2 * tanh_fast(c);
        acc = fmaf(h, c_w[16 + e * 3 + 2], acc);
    }

    out[r] = acc;
}

extern "C" void kernel_launch(void* const* d_in, const int* in_sizes, int n_in,
                              void* d_out, int out_size)
{
    // Input order per metadata: x, w_ih, w_hh, b_ih, b_hh, w_lin, b_lin
    const float* x = (const float*)d_in[0];

    cudaMemcpyToSymbolAsync(c_w, d_in[1],  4 * sizeof(float),  0 * sizeof(float),
                            cudaMemcpyDeviceToDevice, 0);
    cudaMemcpyToSymbolAsync(c_w, d_in[2],  4 * sizeof(float),  4 * sizeof(float),
                            cudaMemcpyDeviceToDevice, 0);
    cudaMemcpyToSymbolAsync(c_w, d_in[3],  4 * sizeof(float),  8 * sizeof(float),
                            cudaMemcpyDeviceToDevice, 0);
    cudaMemcpyToSymbolAsync(c_w, d_in[4],  4 * sizeof(float), 12 * sizeof(float),
                            cudaMemcpyDeviceToDevice, 0);
    cudaMemcpyToSymbolAsync(c_w, d_in[5], 18 * sizeof(float), 16 * sizeof(float),
                            cudaMemcpyDeviceToDevice, 0);
    cudaMemcpyToSymbolAsync(c_w, d_in[6],  1 * sizeof(float), 34 * sizeof(float),
                            cudaMemcpyDeviceToDevice, 0);

    int nrows = out_size;             // 2,097,152 output rows
    int threads = 256;
    int blocks = (nrows + threads - 1) / threads;
    lstm_lin_kernel<<<blocks, threads>>>(x, (float*)d_out, nrows);
}